// round 16
// baseline (speedup 1.0000x reference)
#include <cuda_runtime.h>

#define EPS 1e-5f

#define MAXN   100000
#define MAXN2  50000
#define MAXN3  25000
#define MAXN4  8340
#define MAXE   1600000
#define SPAD   32

// ---------------- scratch (static device globals; no allocation) ----------------
__device__ int    g_deg1[MAXN];
__device__ int    g_deg2[MAXN2];
__device__ int    g_deg3[MAXN3];
__device__ int    g_deg4[MAXN4];
__device__ float  g_dis1[MAXN];
__device__ float  g_dis2[MAXN2];
__device__ float  g_dis3[MAXN3];
__device__ float  g_dis4[MAXN4];
__device__ float  g_y[MAXN];
__device__ float  g_s[MAXN];
__device__ float  g_stat1[4][64 * SPAD];
__device__ float  g_stat2[4][64 * SPAD];
__device__ int    g_cnt[3];
__device__ unsigned g_barA;
__device__ unsigned g_barG;
__device__ __align__(16) int2  g_e2[MAXE];
__device__ __align__(16) int2  g_e3[MAXE / 2];
__device__ __align__(16) int2  g_e4[MAXE / 8];
__device__ __align__(16) float g_a[MAXN2 * 64];
__device__ __align__(16) float g_xw[MAXN2 * 64];   // dis[row]*xw[row] (gather source)
__device__ __align__(16) float g_msg[MAXN2 * 64];  // accumulator (seeded same value)

// ---------------- grid-wide barrier ----------------
__device__ __forceinline__ void grid_barrier() {
    __threadfence();
    __syncthreads();
    if (threadIdx.x == 0) {
        unsigned gen = *(volatile unsigned*)&g_barG;
        unsigned t = atomicAdd(&g_barA, 1u);
        if (t == gridDim.x - 1u) {
            atomicExch(&g_barA, 0u);
            __threadfence();
            atomicExch(&g_barG, gen + 1u);
        } else {
            while (*(volatile unsigned*)&g_barG == gen) __nanosleep(32);
        }
    }
    __syncthreads();
    __threadfence();
}

// ---------------- the whole network in one persistent kernel ----------------
__global__ __launch_bounds__(256, 6)
void k_all(const float* __restrict__ x,
           const float* __restrict__ W1,  const float* __restrict__ b1,
           const float* __restrict__ g1,  const float* __restrict__ be1,
           const float* __restrict__ W2,  const float* __restrict__ b2,
           const float* __restrict__ g2,  const float* __restrict__ be2,
           const float* __restrict__ W3,  const float* __restrict__ b3,
           const float* __restrict__ g3,  const float* __restrict__ be3,
           const float* __restrict__ W4,  const float* __restrict__ b4,
           const float* __restrict__ g4,  const float* __restrict__ be4,
           const float* __restrict__ fcW1, const float* __restrict__ fcb1,
           const float* __restrict__ fcW2, const float* __restrict__ fcb2,
           const int* __restrict__ src, const int* __restrict__ dst,
           float* __restrict__ out,
           int N0, int E, int N2, int N3, int N4, int N5) {
    const int tid = threadIdx.x;
    const int nb = gridDim.x;
    const int gstep = nb * 256;
    const int gid0 = blockIdx.x * 256 + tid;

    // phase-unioned shared memory: P1 staging (24576B) / GEMM Ws+xs (20544B) / FC xr,hb
    __shared__ __align__(16) char u_raw[24704];
    __shared__ float sh1[256], sh2[256];
    __shared__ float s_sc[64], s_sh[64];
    __shared__ float s_cr[10];
    __shared__ int   s_c[3], s_b[3];

    // ---------------- P0: init ----------------
    for (int i = gid0; i < MAXN; i += gstep) { g_deg1[i] = 0; g_s[i] = 0.f; }
    for (int i = gid0; i < MAXN2; i += gstep) g_deg2[i] = 0;
    for (int i = gid0; i < MAXN3; i += gstep) g_deg3[i] = 0;
    for (int i = gid0; i < MAXN4; i += gstep) g_deg4[i] = 0;
    for (int i = gid0; i < 4 * 64 * SPAD; i += gstep) {
        (&g_stat1[0][0])[i] = 0.f;
        (&g_stat2[0][0])[i] = 0.f;
    }
    if (gid0 < 3) g_cnt[gid0] = 0;
    grid_barrier();

    // ---------------- P1: degrees + edge compaction (shared staging) ----------
    {
        int2 (*st)[1024] = (int2(*)[1024])u_raw;
        auto proc = [&](int s, int d) {
            if ((unsigned)s < MAXN && (unsigned)d < MAXN) {
                atomicAdd(&g_deg1[d], 1);
                if (((s | d) & 1) == 0) {
                    int p = atomicAdd(&s_c[0], 1);
                    st[0][p] = make_int2(s >> 1, d >> 1);
                    atomicAdd(&g_deg2[d >> 1], 1);
                }
                if (((s | d) & 3) == 0) {
                    int p = atomicAdd(&s_c[1], 1);
                    st[1][p] = make_int2(s >> 2, d >> 2);
                    atomicAdd(&g_deg3[d >> 2], 1);
                }
                if ((s % 12 == 0) && (d % 12 == 0)) {
                    int p = atomicAdd(&s_c[2], 1);
                    st[2][p] = make_int2(s / 12, d / 12);
                    atomicAdd(&g_deg4[d / 12], 1);
                }
            }
        };
        for (int base = blockIdx.x * 1024; base < E; base += nb * 1024) {
            if (tid < 3) s_c[tid] = 0;
            __syncthreads();
            int e0 = base + tid * 4;
            if (e0 + 3 < E) {
                int4 s4 = *(const int4*)(src + e0);
                int4 d4 = *(const int4*)(dst + e0);
                proc(s4.x, d4.x); proc(s4.y, d4.y);
                proc(s4.z, d4.z); proc(s4.w, d4.w);
            } else {
                for (int e = e0; e < E; e++) proc(src[e], dst[e]);
            }
            __syncthreads();
            if (tid < 3) s_b[tid] = atomicAdd(&g_cnt[tid], s_c[tid]);
            __syncthreads();
            #pragma unroll
            for (int l = 0; l < 3; l++) {
                int n = s_c[l];
                int2* dstp = (l == 0) ? g_e2 : (l == 1) ? g_e3 : g_e4;
                int cap = (l == 0) ? MAXE : (l == 1) ? MAXE / 2 : MAXE / 8;
                int b = s_b[l];
                for (int i = tid; i < n; i += 256) {
                    int idx = b + i;
                    if (idx < cap) dstp[idx] = st[l][i];
                }
            }
            __syncthreads();
        }
    }
    grid_barrier();

    // ---------------- P2: node (dis arrays + y) ----------------
    for (int i = gid0; i < N0; i += gstep) {
        float di = rsqrtf((float)g_deg1[i] + 1.f);
        g_dis1[i] = di;
        g_y[i] = di * x[i];
    }
    for (int i = gid0; i < N2; i += gstep) g_dis2[i] = rsqrtf((float)g_deg2[i] + 1.f);
    for (int i = gid0; i < N3; i += gstep) g_dis3[i] = rsqrtf((float)g_deg3[i] + 1.f);
    for (int i = gid0; i < N4; i += gstep) g_dis4[i] = rsqrtf((float)g_deg4[i] + 1.f);
    grid_barrier();

    // ---------------- P3: layer-1 scalar aggregation ----------------
    for (int base = gid0 * 4; base < E; base += gstep * 4) {
        if (base + 3 < E) {
            int4 s4 = *(const int4*)(src + base);
            int4 d4 = *(const int4*)(dst + base);
            float v0 = ((unsigned)s4.x < MAXN) ? g_y[s4.x] : 0.f;
            float v1 = ((unsigned)s4.y < MAXN) ? g_y[s4.y] : 0.f;
            float v2 = ((unsigned)s4.z < MAXN) ? g_y[s4.z] : 0.f;
            float v3 = ((unsigned)s4.w < MAXN) ? g_y[s4.w] : 0.f;
            if ((unsigned)d4.x < MAXN) atomicAdd(&g_s[d4.x], v0);
            if ((unsigned)d4.y < MAXN) atomicAdd(&g_s[d4.y], v1);
            if ((unsigned)d4.z < MAXN) atomicAdd(&g_s[d4.z], v2);
            if ((unsigned)d4.w < MAXN) atomicAdd(&g_s[d4.w], v3);
        } else {
            for (int e = base; e < E; e++) {
                int s = src[e], d = dst[e];
                if ((unsigned)s < MAXN && (unsigned)d < MAXN)
                    atomicAdd(&g_s[d], g_y[s]);
            }
        }
    }
    grid_barrier();

    // stat flush helper
    auto stat_flush = [&](float ls1, float ls2, int l) {
        sh1[tid] = ls1; sh2[tid] = ls2;
        __syncthreads();
        if (tid < 64) {
            float a1 = sh1[tid] + sh1[tid + 64] + sh1[tid + 128] + sh1[tid + 192];
            float a2 = sh2[tid] + sh2[tid + 64] + sh2[tid + 128] + sh2[tid + 192];
            atomicAdd(&g_stat1[l][tid * SPAD], a1);
            atomicAdd(&g_stat2[l][tid * SPAD], a2);
        }
        __syncthreads();
    };

    // ---------------- P4: pool1 + stats(l=0); per-warp scalar broadcast ----------
    {
        float ls1 = 0.f, ls2 = 0.f;
        int total = N2 * 64;
        int lane = tid & 31;
        for (int idx = gid0; idx < total; idx += gstep) {
            int p = idx >> 6, c = idx & 63;   // p uniform within each warp
            float t = 0.f;
            if (lane == 0) {
                int i0 = 2 * p;
                float d0 = g_dis1[i0];
                t = d0 * (g_s[i0] + d0 * x[i0]);
                int i1 = i0 + 1;
                if (i1 < N0) {
                    float d1 = g_dis1[i1];
                    t += d1 * (g_s[i1] + d1 * x[i1]);
                }
            }
            t = __shfl_sync(0xffffffffu, t, 0);
            float val = 0.5f * t * W1[c] + b1[c];
            g_a[idx] = val;
            ls1 += val; ls2 += val * val;
        }
        stat_flush(ls1, ls2, 0);
    }
    grid_barrier();

    // gemm phase: acc[4], 16-row tiles (register-lean). Writes sv = dis[row]*acc
    // into BOTH g_xw (gather source) and g_msg (self-term seed).
    float* Ws = (float*)u_raw;                        // 16384 B
    float (*xs)[65] = (float(*)[65])(u_raw + 16384);  // 16*65*4 = 4160 B
    auto gemm_phase = [&](int l, int N, const float* W,
                          const float* dis, const float* gam, const float* bet) {
        if (tid < 64) {
            float s1 = g_stat1[l][tid * SPAD], s2 = g_stat2[l][tid * SPAD];
            float m = s1 / (float)N;
            float v = s2 / (float)N - m * m;
            float scv = rsqrtf(v + EPS) * gam[tid];
            s_sc[tid] = scv;
            s_sh[tid] = bet[tid] - m * scv;
        }
        for (int i = tid; i < 4096; i += 256) Ws[i] = W[i];
        __syncthreads();
        int c = tid & 63;
        int rq = tid >> 6;   // 0..3, each handles 4 rows
        for (int t0 = blockIdx.x * 16; t0 < N; t0 += nb * 16) {
            for (int i = tid; i < 1024; i += 256) {
                int r = i >> 6, k = i & 63;
                int row = t0 + r;
                float v = 0.f;
                if (row < N)
                    v = fmaxf(0.f, fmaf(g_a[(size_t)row * 64 + k], s_sc[k], s_sh[k]));
                xs[r][k] = v;
            }
            __syncthreads();
            float a0 = 0.f, a1 = 0.f, a2 = 0.f, a3 = 0.f;
            #pragma unroll
            for (int k = 0; k < 64; k++) {
                float w = Ws[k * 64 + c];
                a0 = fmaf(xs[rq * 4 + 0][k], w, a0);
                a1 = fmaf(xs[rq * 4 + 1][k], w, a1);
                a2 = fmaf(xs[rq * 4 + 2][k], w, a2);
                a3 = fmaf(xs[rq * 4 + 3][k], w, a3);
            }
            float av[4] = {a0, a1, a2, a3};
            #pragma unroll
            for (int j = 0; j < 4; j++) {
                int row = t0 + rq * 4 + j;
                if (row < N) {
                    float sv = dis[row] * av[j];
                    g_xw[(size_t)row * 64 + c] = sv;
                    g_msg[(size_t)row * 64 + c] = sv;
                }
            }
            __syncthreads();
        }
    };

    // econv: pure gather->RED, no per-edge coefficients.
    auto econv_phase = [&](const int2* el, int cnt, int cap) {
        if (cnt > cap) cnt = cap;
        int lane = gid0 & 15;
        int grp  = gid0 >> 4;
        int step = gstep >> 4;
        for (int e = grp; e < cnt; e += step) {
            int2 ed = el[e];
            float4 v = *((const float4*)(g_xw + (size_t)ed.x * 64) + lane);
            float4* pd = (float4*)(g_msg + (size_t)ed.y * 64) + lane;
            asm volatile("red.global.add.v4.f32 [%0], {%1,%2,%3,%4};"
                         :: "l"(pd), "f"(v.x), "f"(v.y), "f"(v.z), "f"(v.w)
                         : "memory");
        }
    };

    // pool: conv_out[r,c] = dis[r]*g_msg[r,c] + b[c] for real rows; mean over S.
    auto pool_phase = [&](int Nin, int Nout, int S, int l,
                          const float* dis, const float* b) {
        float ls1 = 0.f, ls2 = 0.f;
        int total = Nout * 64;
        float inv = 1.f / (float)S;
        for (int idx = gid0; idx < total; idx += gstep) {
            int p = idx >> 6, c = idx & 63;
            float bc = b[c];
            float acc = 0.f;
            int base = p * S;
            for (int q = 0; q < S; q++) {
                int r = base + q;
                if (r < Nin)
                    acc += fmaf(dis[r], g_msg[(size_t)r * 64 + c], bc);
            }
            float val = acc * inv;
            g_a[idx] = val;
            ls1 += val; ls2 += val * val;
        }
        stat_flush(ls1, ls2, l);
    };

    // ---------------- layers 2..4 ----------------
    gemm_phase(0, N2, W2, g_dis2, g1, be1);
    grid_barrier();
    econv_phase(g_e2, g_cnt[0], MAXE);
    grid_barrier();
    pool_phase(N2, N3, 2, 1, g_dis2, b2);
    grid_barrier();

    gemm_phase(1, N3, W3, g_dis3, g2, be2);
    grid_barrier();
    econv_phase(g_e3, g_cnt[1], MAXE / 2);
    grid_barrier();
    pool_phase(N3, N4, 3, 2, g_dis3, b3);
    grid_barrier();

    gemm_phase(2, N4, W4, g_dis4, g3, be3);
    grid_barrier();
    econv_phase(g_e4, g_cnt[2], MAXE / 8);
    grid_barrier();
    pool_phase(N4, N5, 3, 3, g_dis4, b4);
    grid_barrier();

    // ---------------- final: FC head (weights from global) + constant fill -------
    {
        float* xr = (float*)u_raw;        // 2*64 floats
        float* hb = xr + 128;             // 2*128 floats
        if (tid < 64) {
            float s1 = g_stat1[3][tid * SPAD], s2 = g_stat2[3][tid * SPAD];
            float m = s1 / (float)N5;
            float v = s2 / (float)N5 - m * m;
            float scv = rsqrtf(v + EPS) * g4[tid];
            s_sc[tid] = scv;
            s_sh[tid] = be4[tid] - m * scv;
        }
        if (tid < 10) {
            float acc = fcb2[tid];
            for (int k = 0; k < 128; k++)
                acc = fmaf(fmaxf(0.f, fcb1[k]), fcW2[k * 10 + tid], acc);
            s_cr[tid] = acc;
        }
        __syncthreads();

        int sub = tid >> 7;      // 0 or 1 : two rows per iteration
        int t = tid & 127;
        for (int r0 = blockIdx.x * 2; r0 < N5; r0 += nb * 2) {
            int row = r0 + sub;
            bool act = row < N5;
            if (act && t < 64)
                xr[sub * 64 + t] = fmaxf(0.f, fmaf(g_a[(size_t)row * 64 + t],
                                                   s_sc[t], s_sh[t]));
            __syncthreads();
            if (act) {
                float h = fcb1[t];
                #pragma unroll 8
                for (int k = 0; k < 64; k++)
                    h = fmaf(xr[sub * 64 + k], fcW1[k * 128 + t], h);
                hb[sub * 128 + t] = fmaxf(0.f, h);
            }
            __syncthreads();
            if (act && t < 10) {
                float acc = fcb2[t];
                #pragma unroll 8
                for (int k = 0; k < 128; k++)
                    acc = fmaf(hb[sub * 128 + k], fcW2[k * 10 + t], acc);
                out[(size_t)row * 10 + t] = acc;
            }
            __syncthreads();
        }

        // constant fill for padded rows
        long long total = (long long)(N0 - N5) * 10;
        float* outp = out + (size_t)N5 * 10;
        for (long long i = gid0; i < total; i += gstep)
            outp[i] = s_cr[(int)(i % 10)];
    }
}

// ---------------- launch ----------------
extern "C" void kernel_launch(void* const* d_in, const int* in_sizes, int n_in,
                              void* d_out, int out_size) {
    const float* x    = (const float*)d_in[0];
    const float* W1   = (const float*)d_in[1];
    const float* b1   = (const float*)d_in[2];
    const float* g1   = (const float*)d_in[3];
    const float* be1  = (const float*)d_in[4];
    const float* W2   = (const float*)d_in[5];
    const float* b2   = (const float*)d_in[6];
    const float* g2   = (const float*)d_in[7];
    const float* be2  = (const float*)d_in[8];
    const float* W3   = (const float*)d_in[9];
    const float* b3   = (const float*)d_in[10];
    const float* g3   = (const float*)d_in[11];
    const float* be3  = (const float*)d_in[12];
    const float* W4   = (const float*)d_in[13];
    const float* b4   = (const float*)d_in[14];
    const float* g4   = (const float*)d_in[15];
    const float* be4  = (const float*)d_in[16];
    const float* fcW1 = (const float*)d_in[17];
    const float* fcb1 = (const float*)d_in[18];
    const float* fcW2 = (const float*)d_in[19];
    const float* fcb2 = (const float*)d_in[20];
    const int* src = (const int*)d_in[21];  // JAX x64 disabled: int32
    const int* dst = (const int*)d_in[22];

    int N0 = in_sizes[0];
    if (N0 > MAXN) N0 = MAXN;
    int E  = in_sizes[21];
    if (E > MAXE) E = MAXE;
    int N2 = (N0 + 1) / 2;
    int N3 = (N2 + 1) / 2;
    int N4 = (N3 + 2) / 3;
    int N5 = (N4 + 2) / 3;
    float* out = (float*)d_out;

    int dev = 0;
    cudaGetDevice(&dev);
    int sms = 0;
    cudaDeviceGetAttribute(&sms, cudaDevAttrMultiProcessorCount, dev);
    if (sms <= 0) sms = 148;
    int perSM = 0;
    cudaOccupancyMaxActiveBlocksPerMultiprocessor(&perSM, k_all, 256, 0);
    if (perSM < 1) perSM = 1;
    if (perSM > 6) perSM = 6;
    int grid = sms * perSM;

    k_all<<<grid, 256>>>(x, W1, b1, g1, be1, W2, b2, g2, be2,
                         W3, b3, g3, be3, W4, b4, g4, be4,
                         fcW1, fcb1, fcW2, fcb2, src, dst, out,
                         N0, E, N2, N3, N4, N5);
}

// round 17
// speedup vs baseline: 1.0583x; 1.0583x over previous
#include <cuda_runtime.h>

#define EPS 1e-5f

#define MAXN   100000
#define MAXN2  50000
#define MAXN3  25000
#define MAXN4  8340
#define MAXE   1600000
#define SPAD   32

// ---------------- scratch (static device globals; no allocation) ----------------
__device__ int    g_deg1[MAXN];
__device__ int    g_deg2[MAXN2];
__device__ int    g_deg3[MAXN3];
__device__ int    g_deg4[MAXN4];
__device__ float  g_dis1[MAXN];
__device__ float  g_dis2[MAXN2];
__device__ float  g_dis3[MAXN3];
__device__ float  g_dis4[MAXN4];
__device__ float  g_y[MAXN];
__device__ float  g_s[MAXN];
__device__ float  g_stat1[4][64 * SPAD];
__device__ float  g_stat2[4][64 * SPAD];
__device__ int    g_cnt[3];
__device__ unsigned g_barA;
__device__ unsigned g_barG;
__device__ __align__(16) int2  g_e2[MAXE];
__device__ __align__(16) int2  g_e3[MAXE / 2];
__device__ __align__(16) int2  g_e4[MAXE / 8];
__device__ __align__(16) float g_a[MAXN2 * 64];
__device__ __align__(16) float g_xw[MAXN2 * 64];   // dis[row]*xw[row] (gather source)
__device__ __align__(16) float g_msg[MAXN2 * 64];  // accumulator (seeded same value)

// ---------------- grid-wide barrier ----------------
__device__ __forceinline__ void grid_barrier() {
    __threadfence();
    __syncthreads();
    if (threadIdx.x == 0) {
        unsigned gen = *(volatile unsigned*)&g_barG;
        unsigned t = atomicAdd(&g_barA, 1u);
        if (t == gridDim.x - 1u) {
            atomicExch(&g_barA, 0u);
            __threadfence();
            atomicExch(&g_barG, gen + 1u);
        } else {
            while (*(volatile unsigned*)&g_barG == gen) __nanosleep(32);
        }
    }
    __syncthreads();
    __threadfence();
}

// ---------------- the whole network in one persistent kernel ----------------
__global__ __launch_bounds__(256, 4)
void k_all(const float* __restrict__ x,
           const float* __restrict__ W1,  const float* __restrict__ b1,
           const float* __restrict__ g1,  const float* __restrict__ be1,
           const float* __restrict__ W2,  const float* __restrict__ b2,
           const float* __restrict__ g2,  const float* __restrict__ be2,
           const float* __restrict__ W3,  const float* __restrict__ b3,
           const float* __restrict__ g3,  const float* __restrict__ be3,
           const float* __restrict__ W4,  const float* __restrict__ b4,
           const float* __restrict__ g4,  const float* __restrict__ be4,
           const float* __restrict__ fcW1, const float* __restrict__ fcb1,
           const float* __restrict__ fcW2, const float* __restrict__ fcb2,
           const int* __restrict__ src, const int* __restrict__ dst,
           float* __restrict__ out,
           int N0, int E, int N2, int N3, int N4, int N5) {
    const int tid = threadIdx.x;
    const int nb = gridDim.x;
    const int gstep = nb * 256;
    const int gid0 = blockIdx.x * 256 + tid;

    // phase-unioned shared memory
    __shared__ __align__(16) char u_raw[40000];
    __shared__ float sh1[256], sh2[256];
    __shared__ float s_sc[64], s_sh[64];
    __shared__ float s_cr[10];
    __shared__ int   s_c[3], s_b[3];

    // ---------------- P0: init ----------------
    for (int i = gid0; i < MAXN; i += gstep) { g_deg1[i] = 0; g_s[i] = 0.f; }
    for (int i = gid0; i < MAXN2; i += gstep) g_deg2[i] = 0;
    for (int i = gid0; i < MAXN3; i += gstep) g_deg3[i] = 0;
    for (int i = gid0; i < MAXN4; i += gstep) g_deg4[i] = 0;
    for (int i = gid0; i < 4 * 64 * SPAD; i += gstep) {
        (&g_stat1[0][0])[i] = 0.f;
        (&g_stat2[0][0])[i] = 0.f;
    }
    if (gid0 < 3) g_cnt[gid0] = 0;
    grid_barrier();

    // ---------------- P1: degrees + edge compaction (shared staging) ----------
    {
        int2 (*st)[1024] = (int2(*)[1024])u_raw;
        auto proc = [&](int s, int d) {
            if ((unsigned)s < MAXN && (unsigned)d < MAXN) {
                atomicAdd(&g_deg1[d], 1);
                if (((s | d) & 1) == 0) {
                    int p = atomicAdd(&s_c[0], 1);
                    st[0][p] = make_int2(s >> 1, d >> 1);
                    atomicAdd(&g_deg2[d >> 1], 1);
                }
                if (((s | d) & 3) == 0) {
                    int p = atomicAdd(&s_c[1], 1);
                    st[1][p] = make_int2(s >> 2, d >> 2);
                    atomicAdd(&g_deg3[d >> 2], 1);
                }
                if ((s % 12 == 0) && (d % 12 == 0)) {
                    int p = atomicAdd(&s_c[2], 1);
                    st[2][p] = make_int2(s / 12, d / 12);
                    atomicAdd(&g_deg4[d / 12], 1);
                }
            }
        };
        for (int base = blockIdx.x * 1024; base < E; base += nb * 1024) {
            if (tid < 3) s_c[tid] = 0;
            __syncthreads();
            int e0 = base + tid * 4;
            if (e0 + 3 < E) {
                int4 s4 = *(const int4*)(src + e0);
                int4 d4 = *(const int4*)(dst + e0);
                proc(s4.x, d4.x); proc(s4.y, d4.y);
                proc(s4.z, d4.z); proc(s4.w, d4.w);
            } else {
                for (int e = e0; e < E; e++) proc(src[e], dst[e]);
            }
            __syncthreads();
            if (tid < 3) s_b[tid] = atomicAdd(&g_cnt[tid], s_c[tid]);
            __syncthreads();
            #pragma unroll
            for (int l = 0; l < 3; l++) {
                int n = s_c[l];
                int2* dstp = (l == 0) ? g_e2 : (l == 1) ? g_e3 : g_e4;
                int cap = (l == 0) ? MAXE : (l == 1) ? MAXE / 2 : MAXE / 8;
                int b = s_b[l];
                for (int i = tid; i < n; i += 256) {
                    int idx = b + i;
                    if (idx < cap) dstp[idx] = st[l][i];
                }
            }
            __syncthreads();
        }
    }
    grid_barrier();

    // ---------------- P2: node (dis arrays + y) ----------------
    for (int i = gid0; i < N0; i += gstep) {
        float di = rsqrtf((float)g_deg1[i] + 1.f);
        g_dis1[i] = di;
        g_y[i] = di * x[i];
    }
    for (int i = gid0; i < N2; i += gstep) g_dis2[i] = rsqrtf((float)g_deg2[i] + 1.f);
    for (int i = gid0; i < N3; i += gstep) g_dis3[i] = rsqrtf((float)g_deg3[i] + 1.f);
    for (int i = gid0; i < N4; i += gstep) g_dis4[i] = rsqrtf((float)g_deg4[i] + 1.f);
    grid_barrier();

    // ---------------- P3: layer-1 scalar aggregation ----------------
    for (int base = gid0 * 4; base < E; base += gstep * 4) {
        if (base + 3 < E) {
            int4 s4 = *(const int4*)(src + base);
            int4 d4 = *(const int4*)(dst + base);
            float v0 = ((unsigned)s4.x < MAXN) ? g_y[s4.x] : 0.f;
            float v1 = ((unsigned)s4.y < MAXN) ? g_y[s4.y] : 0.f;
            float v2 = ((unsigned)s4.z < MAXN) ? g_y[s4.z] : 0.f;
            float v3 = ((unsigned)s4.w < MAXN) ? g_y[s4.w] : 0.f;
            if ((unsigned)d4.x < MAXN) atomicAdd(&g_s[d4.x], v0);
            if ((unsigned)d4.y < MAXN) atomicAdd(&g_s[d4.y], v1);
            if ((unsigned)d4.z < MAXN) atomicAdd(&g_s[d4.z], v2);
            if ((unsigned)d4.w < MAXN) atomicAdd(&g_s[d4.w], v3);
        } else {
            for (int e = base; e < E; e++) {
                int s = src[e], d = dst[e];
                if ((unsigned)s < MAXN && (unsigned)d < MAXN)
                    atomicAdd(&g_s[d], g_y[s]);
            }
        }
    }
    grid_barrier();

    // stat flush helper
    auto stat_flush = [&](float ls1, float ls2, int l) {
        sh1[tid] = ls1; sh2[tid] = ls2;
        __syncthreads();
        if (tid < 64) {
            float a1 = sh1[tid] + sh1[tid + 64] + sh1[tid + 128] + sh1[tid + 192];
            float a2 = sh2[tid] + sh2[tid + 64] + sh2[tid + 128] + sh2[tid + 192];
            atomicAdd(&g_stat1[l][tid * SPAD], a1);
            atomicAdd(&g_stat2[l][tid * SPAD], a2);
        }
        __syncthreads();
    };

    // ---------------- P4: pool1 + stats(l=0); per-warp scalar broadcast ----------
    {
        float ls1 = 0.f, ls2 = 0.f;
        int total = N2 * 64;
        int lane = tid & 31;
        for (int idx = gid0; idx < total; idx += gstep) {
            int p = idx >> 6, c = idx & 63;   // p uniform within each warp
            float t = 0.f;
            if (lane == 0) {
                int i0 = 2 * p;
                float d0 = g_dis1[i0];
                t = d0 * (g_s[i0] + d0 * x[i0]);
                int i1 = i0 + 1;
                if (i1 < N0) {
                    float d1 = g_dis1[i1];
                    t += d1 * (g_s[i1] + d1 * x[i1]);
                }
            }
            t = __shfl_sync(0xffffffffu, t, 0);
            float val = 0.5f * t * W1[c] + b1[c];
            g_a[idx] = val;
            ls1 += val; ls2 += val * val;
        }
        stat_flush(ls1, ls2, 0);
    }
    grid_barrier();

    // gemm phase: acc[8], 32-row tiles (R15 config). Writes sv = dis[row]*acc
    // into BOTH g_xw (gather source) and g_msg (self-term seed).
    float* Ws = (float*)u_raw;
    float (*xs)[65] = (float(*)[65])(u_raw + 16384);
    auto gemm_phase = [&](int l, int N, const float* W,
                          const float* dis, const float* gam, const float* bet) {
        if (tid < 64) {
            float s1 = g_stat1[l][tid * SPAD], s2 = g_stat2[l][tid * SPAD];
            float m = s1 / (float)N;
            float v = s2 / (float)N - m * m;
            float scv = rsqrtf(v + EPS) * gam[tid];
            s_sc[tid] = scv;
            s_sh[tid] = bet[tid] - m * scv;
        }
        for (int i = tid; i < 4096; i += 256) Ws[i] = W[i];
        __syncthreads();
        int c = tid & 63;
        int rq = tid >> 6;
        for (int t0 = blockIdx.x * 32; t0 < N; t0 += nb * 32) {
            for (int i = tid; i < 2048; i += 256) {
                int r = i >> 6, k = i & 63;
                int row = t0 + r;
                float v = 0.f;
                if (row < N)
                    v = fmaxf(0.f, fmaf(g_a[(size_t)row * 64 + k], s_sc[k], s_sh[k]));
                xs[r][k] = v;
            }
            __syncthreads();
            float acc[8] = {0.f, 0.f, 0.f, 0.f, 0.f, 0.f, 0.f, 0.f};
            #pragma unroll
            for (int k = 0; k < 64; k++) {
                float w = Ws[k * 64 + c];
                #pragma unroll
                for (int j = 0; j < 8; j++) acc[j] = fmaf(xs[rq * 8 + j][k], w, acc[j]);
            }
            #pragma unroll
            for (int j = 0; j < 8; j++) {
                int row = t0 + rq * 8 + j;
                if (row < N) {
                    float sv = dis[row] * acc[j];
                    g_xw[(size_t)row * 64 + c] = sv;
                    g_msg[(size_t)row * 64 + c] = sv;
                }
            }
            __syncthreads();
        }
    };

    // econv: pure gather->RED, 2-way software pipeline for MLP=2.
    auto econv_phase = [&](const int2* el, int cnt, int cap) {
        if (cnt > cap) cnt = cap;
        int lane = gid0 & 15;
        int grp  = gid0 >> 4;
        int step = gstep >> 4;
        int e = grp;
        for (; e + step < cnt; e += 2 * step) {
            int2 ed0 = el[e];
            int2 ed1 = el[e + step];
            float4 v0 = *((const float4*)(g_xw + (size_t)ed0.x * 64) + lane);
            float4 v1 = *((const float4*)(g_xw + (size_t)ed1.x * 64) + lane);
            float4* p0 = (float4*)(g_msg + (size_t)ed0.y * 64) + lane;
            float4* p1 = (float4*)(g_msg + (size_t)ed1.y * 64) + lane;
            asm volatile("red.global.add.v4.f32 [%0], {%1,%2,%3,%4};"
                         :: "l"(p0), "f"(v0.x), "f"(v0.y), "f"(v0.z), "f"(v0.w)
                         : "memory");
            asm volatile("red.global.add.v4.f32 [%0], {%1,%2,%3,%4};"
                         :: "l"(p1), "f"(v1.x), "f"(v1.y), "f"(v1.z), "f"(v1.w)
                         : "memory");
        }
        if (e < cnt) {
            int2 ed = el[e];
            float4 v = *((const float4*)(g_xw + (size_t)ed.x * 64) + lane);
            float4* pd = (float4*)(g_msg + (size_t)ed.y * 64) + lane;
            asm volatile("red.global.add.v4.f32 [%0], {%1,%2,%3,%4};"
                         :: "l"(pd), "f"(v.x), "f"(v.y), "f"(v.z), "f"(v.w)
                         : "memory");
        }
    };

    // pool: conv_out[r,c] = dis[r]*g_msg[r,c] + b[c] for real rows; mean over S.
    auto pool_phase = [&](int Nin, int Nout, int S, int l,
                          const float* dis, const float* b) {
        float ls1 = 0.f, ls2 = 0.f;
        int total = Nout * 64;
        float inv = 1.f / (float)S;
        for (int idx = gid0; idx < total; idx += gstep) {
            int p = idx >> 6, c = idx & 63;
            float bc = b[c];
            float acc = 0.f;
            int base = p * S;
            for (int q = 0; q < S; q++) {
                int r = base + q;
                if (r < Nin)
                    acc += fmaf(dis[r], g_msg[(size_t)r * 64 + c], bc);
            }
            float val = acc * inv;
            g_a[idx] = val;
            ls1 += val; ls2 += val * val;
        }
        stat_flush(ls1, ls2, l);
    };

    // ---------------- layers 2..4 ----------------
    gemm_phase(0, N2, W2, g_dis2, g1, be1);
    grid_barrier();
    econv_phase(g_e2, g_cnt[0], MAXE);
    grid_barrier();
    pool_phase(N2, N3, 2, 1, g_dis2, b2);
    grid_barrier();

    gemm_phase(1, N3, W3, g_dis3, g2, be2);
    grid_barrier();
    econv_phase(g_e3, g_cnt[1], MAXE / 2);
    grid_barrier();
    pool_phase(N3, N4, 3, 2, g_dis3, b3);
    grid_barrier();

    gemm_phase(2, N4, W4, g_dis4, g3, be3);
    grid_barrier();
    econv_phase(g_e4, g_cnt[2], MAXE / 8);
    grid_barrier();
    pool_phase(N4, N5, 3, 3, g_dis4, b4);
    grid_barrier();

    // ---------------- final: FC head + constant fill ----------------
    {
        float* W1s = (float*)u_raw;                       // 8192 floats
        float* W2s = (float*)(u_raw + 32768);             // 1280 floats
        float* xr  = (float*)(u_raw + 32768 + 5120);      // 2*64
        float* hb  = xr + 128;                            // 2*128
        if (tid < 64) {
            float s1 = g_stat1[3][tid * SPAD], s2 = g_stat2[3][tid * SPAD];
            float m = s1 / (float)N5;
            float v = s2 / (float)N5 - m * m;
            float scv = rsqrtf(v + EPS) * g4[tid];
            s_sc[tid] = scv;
            s_sh[tid] = be4[tid] - m * scv;
        }
        for (int i = tid; i < 8192; i += 256) W1s[i] = fcW1[i];
        for (int i = tid; i < 1280; i += 256) W2s[i] = fcW2[i];
        if (tid < 10) {
            float acc = fcb2[tid];
            for (int k = 0; k < 128; k++)
                acc = fmaf(fmaxf(0.f, fcb1[k]), fcW2[k * 10 + tid], acc);
            s_cr[tid] = acc;
        }
        __syncthreads();

        int sub = tid >> 7;      // 0 or 1 : two rows per iteration
        int t = tid & 127;
        for (int r0 = blockIdx.x * 2; r0 < N5; r0 += nb * 2) {
            int row = r0 + sub;
            bool act = row < N5;
            if (act && t < 64)
                xr[sub * 64 + t] = fmaxf(0.f, fmaf(g_a[(size_t)row * 64 + t],
                                                   s_sc[t], s_sh[t]));
            __syncthreads();
            if (act) {
                float h = fcb1[t];
                #pragma unroll
                for (int k = 0; k < 64; k++)
                    h = fmaf(xr[sub * 64 + k], W1s[k * 128 + t], h);
                hb[sub * 128 + t] = fmaxf(0.f, h);
            }
            __syncthreads();
            if (act && t < 10) {
                float acc = fcb2[t];
                #pragma unroll 8
                for (int k = 0; k < 128; k++)
                    acc = fmaf(hb[sub * 128 + k], W2s[k * 10 + t], acc);
                out[(size_t)row * 10 + t] = acc;
            }
            __syncthreads();
        }

        // constant fill for padded rows
        long long total = (long long)(N0 - N5) * 10;
        float* outp = out + (size_t)N5 * 10;
        for (long long i = gid0; i < total; i += gstep)
            outp[i] = s_cr[(int)(i % 10)];
    }
}

// ---------------- launch ----------------
extern "C" void kernel_launch(void* const* d_in, const int* in_sizes, int n_in,
                              void* d_out, int out_size) {
    const float* x    = (const float*)d_in[0];
    const float* W1   = (const float*)d_in[1];
    const float* b1   = (const float*)d_in[2];
    const float* g1   = (const float*)d_in[3];
    const float* be1  = (const float*)d_in[4];
    const float* W2   = (const float*)d_in[5];
    const float* b2   = (const float*)d_in[6];
    const float* g2   = (const float*)d_in[7];
    const float* be2  = (const float*)d_in[8];
    const float* W3   = (const float*)d_in[9];
    const float* b3   = (const float*)d_in[10];
    const float* g3   = (const float*)d_in[11];
    const float* be3  = (const float*)d_in[12];
    const float* W4   = (const float*)d_in[13];
    const float* b4   = (const float*)d_in[14];
    const float* g4   = (const float*)d_in[15];
    const float* be4  = (const float*)d_in[16];
    const float* fcW1 = (const float*)d_in[17];
    const float* fcb1 = (const float*)d_in[18];
    const float* fcW2 = (const float*)d_in[19];
    const float* fcb2 = (const float*)d_in[20];
    const int* src = (const int*)d_in[21];  // JAX x64 disabled: int32
    const int* dst = (const int*)d_in[22];

    int N0 = in_sizes[0];
    if (N0 > MAXN) N0 = MAXN;
    int E  = in_sizes[21];
    if (E > MAXE) E = MAXE;
    int N2 = (N0 + 1) / 2;
    int N3 = (N2 + 1) / 2;
    int N4 = (N3 + 2) / 3;
    int N5 = (N4 + 2) / 3;
    float* out = (float*)d_out;

    // 4 blocks/SM sweet spot (confirmed: 6 blocks regresses via reg pressure)
    int dev = 0;
    cudaGetDevice(&dev);
    int sms = 0;
    cudaDeviceGetAttribute(&sms, cudaDevAttrMultiProcessorCount, dev);
    if (sms <= 0) sms = 148;
    int perSM = 0;
    cudaOccupancyMaxActiveBlocksPerMultiprocessor(&perSM, k_all, 256, 0);
    if (perSM < 1) perSM = 1;
    if (perSM > 4) perSM = 4;
    int grid = sms * perSM;

    k_all<<<grid, 256>>>(x, W1, b1, g1, be1, W2, b2, g2, be2,
                         W3, b3, g3, be3, W4, b4, g4, be4,
                         fcW1, fcb1, fcW2, fcb2, src, dst, out,
                         N0, E, N2, N3, N4, N5);
}